// round 1
// baseline (speedup 1.0000x reference)
#include <cuda_runtime.h>

#define BATCH 2
#define SEQ   2048
#define DM    2048
#define NH    16
#define HD    128
#define KVD   256
#define MTOT  (BATCH*SEQ)

// Scratch (no allocations allowed): Q proj out, KV proj out, attention out.
__device__ float gQ[MTOT * DM];     // [b*s][2048], col = h*128+d
__device__ float gKV[MTOT * KVD];   // [b*s][256], k=0..127, v=128..255
__device__ float gO[MTOT * DM];     // attention output, [b*s][h*128+d]

// ---------------------------------------------------------------------------
// SGEMM, NT layout: C[M,N] = A[M,K] * B[N,K]^T. A,B row-major, K contiguous.
// 64x64 tile, BK=16, 256 threads, 4x4 micro-tile per thread.
// ---------------------------------------------------------------------------
__global__ void __launch_bounds__(256)
gemm_nt64(const float* __restrict__ A, const float* __restrict__ B,
          float* __restrict__ C, int N, int K)
{
    __shared__ float sA[16][64];   // [k][m] transposed staging
    __shared__ float sB[16][64];   // [k][n]

    const int tid = threadIdx.x;
    const int tx  = tid & 15;          // 0..15 -> n
    const int ty  = tid >> 4;          // 0..15 -> m
    const int m0  = blockIdx.y * 64;
    const int n0  = blockIdx.x * 64;

    const int lr = tid >> 2;           // 0..63 row within tile
    const int lk = (tid & 3) * 4;      // 0,4,8,12 k offset

    float acc[4][4] = {};

    for (int k0 = 0; k0 < K; k0 += 16) {
        float4 av = *(const float4*)&A[(size_t)(m0 + lr) * K + k0 + lk];
        float4 bv = *(const float4*)&B[(size_t)(n0 + lr) * K + k0 + lk];
        __syncthreads();   // previous tile's compute done before overwrite
        sA[lk + 0][lr] = av.x; sA[lk + 1][lr] = av.y;
        sA[lk + 2][lr] = av.z; sA[lk + 3][lr] = av.w;
        sB[lk + 0][lr] = bv.x; sB[lk + 1][lr] = bv.y;
        sB[lk + 2][lr] = bv.z; sB[lk + 3][lr] = bv.w;
        __syncthreads();

#pragma unroll
        for (int kk = 0; kk < 16; kk++) {
            float4 a = *(const float4*)&sA[kk][ty * 4];
            float4 b = *(const float4*)&sB[kk][tx * 4];
            acc[0][0] += a.x * b.x; acc[0][1] += a.x * b.y;
            acc[0][2] += a.x * b.z; acc[0][3] += a.x * b.w;
            acc[1][0] += a.y * b.x; acc[1][1] += a.y * b.y;
            acc[1][2] += a.y * b.z; acc[1][3] += a.y * b.w;
            acc[2][0] += a.z * b.x; acc[2][1] += a.z * b.y;
            acc[2][2] += a.z * b.z; acc[2][3] += a.z * b.w;
            acc[3][0] += a.w * b.x; acc[3][1] += a.w * b.y;
            acc[3][2] += a.w * b.z; acc[3][3] += a.w * b.w;
        }
    }

#pragma unroll
    for (int i = 0; i < 4; i++) {
        float4 st = make_float4(acc[i][0], acc[i][1], acc[i][2], acc[i][3]);
        *(float4*)&C[(size_t)(m0 + ty * 4 + i) * N + n0 + tx * 4] = st;
    }
}

// ---------------------------------------------------------------------------
// Flash attention, causal MQA. One block = 64 query rows of one (b,h) pair.
// 256 threads. smem rows padded (129 / 65 floats) to avoid bank conflicts.
// ---------------------------------------------------------------------------
#define ATTN_SMEM_FLOATS (64*129 + 64*129 + 64*65 + 64*3)
#define ATTN_SMEM_BYTES  (ATTN_SMEM_FLOATS * 4)

__global__ void __launch_bounds__(256)
attn_kernel()
{
    extern __shared__ float sm[];
    float* sQ  = sm;                  // [64][129]
    float* sK  = sQ + 64 * 129;       // [64][129] (K tile, then reused for V)
    float* sS  = sK + 64 * 129;       // [64][65]  scores / probs
    float* sM  = sS + 64 * 65;        // [64] running max
    float* sL  = sM + 64;             // [64] running sum
    float* sAl = sL + 64;             // [64] correction alpha

    const int tid = threadIdx.x;
    const int qb  = blockIdx.x;                 // query block (0..31)
    const int b   = blockIdx.y >> 4;
    const int h   = blockIdx.y & 15;
    const int tx  = tid & 15;
    const int ty  = tid >> 4;
    const int ty4 = ty * 4;
    const int tx4 = tx * 4;
    const int tx8 = tx * 8;

    const float scale = 0.08838834764831845f;   // 1/sqrt(128)

    // ---- load Q tile: 64 rows x 128 cols ----
    const float* Qbase = gQ + ((size_t)(b * SEQ + qb * 64)) * DM + h * HD;
#pragma unroll
    for (int it = 0; it < 8; it++) {
        int idx = tid + it * 256;               // float4 index, 2048 total
        int row = idx >> 5;
        int cs  = (idx & 31) << 2;
        float4 v = *(const float4*)&Qbase[(size_t)row * DM + cs];
        float* p = &sQ[row * 129 + cs];
        p[0] = v.x; p[1] = v.y; p[2] = v.z; p[3] = v.w;
    }
    if (tid < 64) { sM[tid] = -1e30f; sL[tid] = 0.0f; }

    float o[4][8] = {};

    for (int j = 0; j <= qb; j++) {
        const float* KVbase = gKV + ((size_t)(b * SEQ + j * 64)) * KVD;

        __syncthreads();   // prev PV done with sK(V) and sS
        // ---- load K tile ----
#pragma unroll
        for (int it = 0; it < 8; it++) {
            int idx = tid + it * 256;
            int row = idx >> 5;
            int cs  = (idx & 31) << 2;
            float4 v = *(const float4*)&KVbase[row * KVD + cs];
            float* p = &sK[row * 129 + cs];
            p[0] = v.x; p[1] = v.y; p[2] = v.z; p[3] = v.w;
        }
        __syncthreads();

        // ---- S = scale * Q K^T (4x4 per thread), causal mask ----
        float s[4][4] = {};
#pragma unroll 4
        for (int kk = 0; kk < HD; kk++) {
            float a[4], bb[4];
#pragma unroll
            for (int i = 0; i < 4; i++) a[i]  = sQ[(ty4 + i) * 129 + kk];
#pragma unroll
            for (int i = 0; i < 4; i++) bb[i] = sK[(tx4 + i) * 129 + kk];
#pragma unroll
            for (int i = 0; i < 4; i++)
#pragma unroll
                for (int jj = 0; jj < 4; jj++) s[i][jj] += a[i] * bb[jj];
        }
#pragma unroll
        for (int i = 0; i < 4; i++) {
            int rg = qb * 64 + ty4 + i;
#pragma unroll
            for (int jj = 0; jj < 4; jj++) {
                int cg = j * 64 + tx4 + jj;
                float val = s[i][jj] * scale;
                if (cg > rg) val = -1e30f;      // causal mask
                sS[(ty4 + i) * 65 + tx4 + jj] = val;
            }
        }
        __syncthreads();

        // ---- load V tile into sK (S-compute reads of sK are done) ----
#pragma unroll
        for (int it = 0; it < 8; it++) {
            int idx = tid + it * 256;
            int row = idx >> 5;
            int cs  = (idx & 31) << 2;
            float4 v = *(const float4*)&KVbase[row * KVD + 128 + cs];
            float* p = &sK[row * 129 + cs];
            p[0] = v.x; p[1] = v.y; p[2] = v.z; p[3] = v.w;
        }

        // ---- online softmax, one thread per row ----
        if (tid < 64) {
            float mold = sM[tid];
            float mt = -1e30f;
#pragma unroll 8
            for (int c = 0; c < 64; c++) mt = fmaxf(mt, sS[tid * 65 + c]);
            float mnew  = fmaxf(mold, mt);
            float alpha = __expf(mold - mnew);
            float sum = 0.0f;
#pragma unroll 8
            for (int c = 0; c < 64; c++) {
                float p = __expf(sS[tid * 65 + c] - mnew);
                sS[tid * 65 + c] = p;
                sum += p;
            }
            sM[tid]  = mnew;
            sL[tid]  = sL[tid] * alpha + sum;
            sAl[tid] = alpha;
        }
        __syncthreads();

        // ---- O = O*alpha + P V ----
        float al[4];
#pragma unroll
        for (int i = 0; i < 4; i++) al[i] = sAl[ty4 + i];
#pragma unroll
        for (int i = 0; i < 4; i++)
#pragma unroll
            for (int jj = 0; jj < 8; jj++) o[i][jj] *= al[i];

#pragma unroll 2
        for (int kk = 0; kk < 64; kk++) {
            float p[4], v[8];
#pragma unroll
            for (int i = 0; i < 4; i++)  p[i] = sS[(ty4 + i) * 65 + kk];
#pragma unroll
            for (int jj = 0; jj < 8; jj++) v[jj] = sK[kk * 129 + tx8 + jj];
#pragma unroll
            for (int i = 0; i < 4; i++)
#pragma unroll
                for (int jj = 0; jj < 8; jj++) o[i][jj] += p[i] * v[jj];
        }
    }

    // ---- normalize and write out ----
    float inv[4];
#pragma unroll
    for (int i = 0; i < 4; i++) inv[i] = 1.0f / sL[ty4 + i];

    float* Obase = gO + ((size_t)(b * SEQ + qb * 64)) * DM + h * HD;
#pragma unroll
    for (int i = 0; i < 4; i++) {
        float4 lo = make_float4(o[i][0] * inv[i], o[i][1] * inv[i],
                                o[i][2] * inv[i], o[i][3] * inv[i]);
        float4 hi = make_float4(o[i][4] * inv[i], o[i][5] * inv[i],
                                o[i][6] * inv[i], o[i][7] * inv[i]);
        *(float4*)&Obase[(size_t)(ty4 + i) * DM + tx8]     = lo;
        *(float4*)&Obase[(size_t)(ty4 + i) * DM + tx8 + 4] = hi;
    }
}

// ---------------------------------------------------------------------------
extern "C" void kernel_launch(void* const* d_in, const int* in_sizes, int n_in,
                              void* d_out, int out_size)
{
    const float* x   = (const float*)d_in[0];
    const float* Wq  = (const float*)d_in[1];
    const float* Wkv = (const float*)d_in[2];
    const float* Wo  = (const float*)d_in[3];
    float* out = (float*)d_out;

    float *pQ, *pKV, *pO;
    cudaGetSymbolAddress((void**)&pQ,  gQ);
    cudaGetSymbolAddress((void**)&pKV, gKV);
    cudaGetSymbolAddress((void**)&pO,  gO);

    cudaFuncSetAttribute(attn_kernel,
                         cudaFuncAttributeMaxDynamicSharedMemorySize,
                         ATTN_SMEM_BYTES);

    // Q projection: [4096,2048] = x @ Wq^T
    gemm_nt64<<<dim3(DM / 64, MTOT / 64), 256>>>(x, Wq, pQ, DM, DM);
    // KV projection: [4096,256] = x @ Wkv^T
    gemm_nt64<<<dim3(KVD / 64, MTOT / 64), 256>>>(x, Wkv, pKV, KVD, DM);
    // Attention: 32 query blocks x 32 (b,h) pairs
    attn_kernel<<<dim3(SEQ / 64, BATCH * NH), 256, ATTN_SMEM_BYTES>>>();
    // O projection: out = attnO @ Wo^T
    gemm_nt64<<<dim3(DM / 64, MTOT / 64), 256>>>(pO, Wo, out, DM, DM);
}

// round 3
// speedup vs baseline: 1.4386x; 1.4386x over previous
#include <cuda_runtime.h>
#include <cuda_bf16.h>
#include <cstdint>

#define BATCH 2
#define SEQ   2048
#define DM    2048
#define NH    16
#define HD    128
#define KVD   256
#define MTOT  (BATCH*SEQ)

// fp32 scratch
__device__ float gQ[MTOT * DM];
__device__ float gKV[MTOT * KVD];
__device__ float gO[MTOT * DM];
// bf16 hi/lo scratch (pre-converted operands)
__device__ __nv_bfloat16 g_xh[MTOT * DM],  g_xl[MTOT * DM];
__device__ __nv_bfloat16 g_wqh[DM * DM],   g_wql[DM * DM];
__device__ __nv_bfloat16 g_wkvh[KVD * DM], g_wkvl[KVD * DM];
__device__ __nv_bfloat16 g_woh[DM * DM],   g_wol[DM * DM];
__device__ __nv_bfloat16 g_oh[MTOT * DM],  g_ol[MTOT * DM];

// ===========================================================================
// helpers
// ===========================================================================
__device__ __forceinline__ uint32_t smem_u32(const void* p) {
    uint32_t a;
    asm("{ .reg .u64 t; cvta.to.shared.u64 t, %1; cvt.u32.u64 %0, t; }"
        : "=r"(a) : "l"(p));
    return a;
}

#define CP16(dst, src) \
    asm volatile("cp.async.cg.shared.global [%0], [%1], 16;" \
                 :: "r"(dst), "l"(src))
#define CP_COMMIT() asm volatile("cp.async.commit_group;")
#define CP_WAIT(n)  asm volatile("cp.async.wait_group %0;" :: "n"(n))

#define LDSM4(r, addr)                                                        \
    asm volatile("ldmatrix.sync.aligned.m8n8.x4.shared.b16 {%0,%1,%2,%3}, [%4];" \
        : "=r"((r)[0]), "=r"((r)[1]), "=r"((r)[2]), "=r"((r)[3]) : "r"(addr))
#define LDSM2(r, addr)                                                        \
    asm volatile("ldmatrix.sync.aligned.m8n8.x2.shared.b16 {%0,%1}, [%2];"    \
        : "=r"((r)[0]), "=r"((r)[1]) : "r"(addr))

#define MMA16816(c, a, b)                                                     \
    asm volatile("mma.sync.aligned.m16n8k16.row.col.f32.bf16.bf16.f32 "       \
        "{%0,%1,%2,%3}, {%4,%5,%6,%7}, {%8,%9}, {%0,%1,%2,%3};"               \
        : "+f"((c)[0]), "+f"((c)[1]), "+f"((c)[2]), "+f"((c)[3])              \
        : "r"((a)[0]), "r"((a)[1]), "r"((a)[2]), "r"((a)[3]),                 \
          "r"((b)[0]), "r"((b)[1]))

// ===========================================================================
// fp32 -> bf16 hi/lo conversion (bandwidth-bound pass)
// ===========================================================================
__global__ void __launch_bounds__(256)
cvt_hilo(const float4* __restrict__ in, uint2* __restrict__ hi,
         uint2* __restrict__ lo, int n4)
{
    int i = blockIdx.x * blockDim.x + threadIdx.x;
    if (i >= n4) return;
    float4 f = in[i];
    __nv_bfloat162 h0 = __floats2bfloat162_rn(f.x, f.y);
    __nv_bfloat162 h1 = __floats2bfloat162_rn(f.z, f.w);
    __nv_bfloat162 l0 = __floats2bfloat162_rn(f.x - __bfloat162float(h0.x),
                                              f.y - __bfloat162float(h0.y));
    __nv_bfloat162 l1 = __floats2bfloat162_rn(f.z - __bfloat162float(h1.x),
                                              f.w - __bfloat162float(h1.y));
    hi[i] = make_uint2(*(uint32_t*)&h0, *(uint32_t*)&h1);
    lo[i] = make_uint2(*(uint32_t*)&l0, *(uint32_t*)&l1);
}

// ===========================================================================
// bf16x3 mma.sync GEMM: C[M,N] = A[M,K] * B[N,K]^T  (A,B as bf16 hi/lo pairs)
// CTA tile 128x128, BK=32, 256 threads (8 warps: 2m x 4n, 64x32 each).
// smem: 2 stages x 4 buffers (Ahi,Alo,Bhi,Blo) x [128 rows x 80B].
// ===========================================================================
#define GSTAGE   40960
#define GBUF     10240
#define GEMM_SMEM (2 * GSTAGE)

__global__ void __launch_bounds__(256, 1)
gemm_mma(const __nv_bfloat16* __restrict__ Ah, const __nv_bfloat16* __restrict__ Al,
         const __nv_bfloat16* __restrict__ Bh, const __nv_bfloat16* __restrict__ Bl,
         float* __restrict__ C, int N, int K)
{
    extern __shared__ char smem[];
    const uint32_t sbase = smem_u32(smem);

    const int tid  = threadIdx.x;
    const int lane = tid & 31;
    const int wid  = tid >> 5;
    const int wm   = (wid >> 2) * 64;
    const int wn   = (wid & 3) * 32;
    const int m0   = blockIdx.y * 128;
    const int n0   = blockIdx.x * 128;

    // load mapping: thread -> (row, 2 chunks of 16B)
    const int lrow = tid >> 1;            // 0..127
    const int lc   = (tid & 1) * 2;       // chunk 0 or 2

    const __nv_bfloat16* gsrc[4];
    gsrc[0] = Ah + (size_t)(m0 + lrow) * K;
    gsrc[1] = Al + (size_t)(m0 + lrow) * K;
    gsrc[2] = Bh + (size_t)(n0 + lrow) * K;
    gsrc[3] = Bl + (size_t)(n0 + lrow) * K;
    const uint32_t drow = sbase + lrow * 80 + lc * 16;

    float acc[4][4][4] = {};

    const int NIT = K >> 5;

    // prologue: stage 0
#pragma unroll
    for (int buf = 0; buf < 4; buf++) {
        CP16(drow + buf * GBUF,            gsrc[buf] + lc * 8);
        CP16(drow + buf * GBUF + 16,       gsrc[buf] + lc * 8 + 8);
    }
    CP_COMMIT();

    for (int kt = 0; kt < NIT; kt++) {
        if (kt + 1 < NIT) {
            const int kb = (kt + 1) << 5;
            const uint32_t d = drow + ((kt + 1) & 1) * GSTAGE;
#pragma unroll
            for (int buf = 0; buf < 4; buf++) {
                CP16(d + buf * GBUF,      gsrc[buf] + kb + lc * 8);
                CP16(d + buf * GBUF + 16, gsrc[buf] + kb + lc * 8 + 8);
            }
            CP_COMMIT();
            CP_WAIT(1);
        } else {
            CP_WAIT(0);
        }
        __syncthreads();

        const uint32_t sb = sbase + (kt & 1) * GSTAGE;
#pragma unroll
        for (int ks = 0; ks < 2; ks++) {
            uint32_t ah[4][4], al[4][4], bh[4][2], bl[4][2];
#pragma unroll
            for (int mi = 0; mi < 4; mi++) {
                uint32_t aaddr = sb + (wm + mi * 16 + (lane & 15)) * 80
                               + ks * 32 + (lane >> 4) * 16;
                LDSM4(ah[mi], aaddr);
                LDSM4(al[mi], aaddr + GBUF);
            }
#pragma unroll
            for (int ni = 0; ni < 4; ni++) {
                uint32_t baddr = sb + 2 * GBUF + (wn + ni * 8 + (lane & 7)) * 80
                               + ks * 32 + ((lane >> 3) & 1) * 16;
                LDSM2(bh[ni], baddr);
                LDSM2(bl[ni], baddr + GBUF);
            }
#pragma unroll
            for (int mi = 0; mi < 4; mi++)
#pragma unroll
                for (int ni = 0; ni < 4; ni++) {
                    MMA16816(acc[mi][ni], ah[mi], bh[ni]);
                    MMA16816(acc[mi][ni], ah[mi], bl[ni]);
                    MMA16816(acc[mi][ni], al[mi], bh[ni]);
                }
        }
        __syncthreads();
    }

    // epilogue
    const int rg = lane >> 2;
    const int cg = (lane & 3) * 2;
#pragma unroll
    for (int mi = 0; mi < 4; mi++) {
#pragma unroll
        for (int ni = 0; ni < 4; ni++) {
            int r = m0 + wm + mi * 16 + rg;
            int c = n0 + wn + ni * 8 + cg;
            *(float2*)&C[(size_t)r * N + c] =
                make_float2(acc[mi][ni][0], acc[mi][ni][1]);
            *(float2*)&C[(size_t)(r + 8) * N + c] =
                make_float2(acc[mi][ni][2], acc[mi][ni][3]);
        }
    }
}

// ===========================================================================
// Flash attention (unchanged): causal MQA, fp32 SIMT
// ===========================================================================
#define ATTN_SMEM_FLOATS (64*129 + 64*129 + 64*65 + 64*3)
#define ATTN_SMEM_BYTES  (ATTN_SMEM_FLOATS * 4)

__global__ void __launch_bounds__(256)
attn_kernel()
{
    extern __shared__ float sm[];
    float* sQ  = sm;
    float* sK  = sQ + 64 * 129;
    float* sS  = sK + 64 * 129;
    float* sM  = sS + 64 * 65;
    float* sL  = sM + 64;
    float* sAl = sL + 64;

    const int tid = threadIdx.x;
    const int qb  = blockIdx.x;
    const int b   = blockIdx.y >> 4;
    const int h   = blockIdx.y & 15;
    const int tx  = tid & 15;
    const int ty  = tid >> 4;
    const int ty4 = ty * 4;
    const int tx4 = tx * 4;
    const int tx8 = tx * 8;

    const float scale = 0.08838834764831845f;

    const float* Qbase = gQ + ((size_t)(b * SEQ + qb * 64)) * DM + h * HD;
#pragma unroll
    for (int it = 0; it < 8; it++) {
        int idx = tid + it * 256;
        int row = idx >> 5;
        int cs  = (idx & 31) << 2;
        float4 v = *(const float4*)&Qbase[(size_t)row * DM + cs];
        float* p = &sQ[row * 129 + cs];
        p[0] = v.x; p[1] = v.y; p[2] = v.z; p[3] = v.w;
    }
    if (tid < 64) { sM[tid] = -1e30f; sL[tid] = 0.0f; }

    float o[4][8] = {};

    for (int j = 0; j <= qb; j++) {
        const float* KVbase = gKV + ((size_t)(b * SEQ + j * 64)) * KVD;

        __syncthreads();
#pragma unroll
        for (int it = 0; it < 8; it++) {
            int idx = tid + it * 256;
            int row = idx >> 5;
            int cs  = (idx & 31) << 2;
            float4 v = *(const float4*)&KVbase[row * KVD + cs];
            float* p = &sK[row * 129 + cs];
            p[0] = v.x; p[1] = v.y; p[2] = v.z; p[3] = v.w;
        }
        __syncthreads();

        float s[4][4] = {};
#pragma unroll 4
        for (int kk = 0; kk < HD; kk++) {
            float a[4], bb[4];
#pragma unroll
            for (int i = 0; i < 4; i++) a[i]  = sQ[(ty4 + i) * 129 + kk];
#pragma unroll
            for (int i = 0; i < 4; i++) bb[i] = sK[(tx4 + i) * 129 + kk];
#pragma unroll
            for (int i = 0; i < 4; i++)
#pragma unroll
                for (int jj = 0; jj < 4; jj++) s[i][jj] += a[i] * bb[jj];
        }
#pragma unroll
        for (int i = 0; i < 4; i++) {
            int rg = qb * 64 + ty4 + i;
#pragma unroll
            for (int jj = 0; jj < 4; jj++) {
                int cg2 = j * 64 + tx4 + jj;
                float val = s[i][jj] * scale;
                if (cg2 > rg) val = -1e30f;
                sS[(ty4 + i) * 65 + tx4 + jj] = val;
            }
        }
        __syncthreads();

#pragma unroll
        for (int it = 0; it < 8; it++) {
            int idx = tid + it * 256;
            int row = idx >> 5;
            int cs  = (idx & 31) << 2;
            float4 v = *(const float4*)&KVbase[row * KVD + 128 + cs];
            float* p = &sK[row * 129 + cs];
            p[0] = v.x; p[1] = v.y; p[2] = v.z; p[3] = v.w;
        }

        if (tid < 64) {
            float mold = sM[tid];
            float mt = -1e30f;
#pragma unroll 8
            for (int c = 0; c < 64; c++) mt = fmaxf(mt, sS[tid * 65 + c]);
            float mnew  = fmaxf(mold, mt);
            float alpha = __expf(mold - mnew);
            float sum = 0.0f;
#pragma unroll 8
            for (int c = 0; c < 64; c++) {
                float p = __expf(sS[tid * 65 + c] - mnew);
                sS[tid * 65 + c] = p;
                sum += p;
            }
            sM[tid]  = mnew;
            sL[tid]  = sL[tid] * alpha + sum;
            sAl[tid] = alpha;
        }
        __syncthreads();

        float al[4];
#pragma unroll
        for (int i = 0; i < 4; i++) al[i] = sAl[ty4 + i];
#pragma unroll
        for (int i = 0; i < 4; i++)
#pragma unroll
            for (int jj = 0; jj < 8; jj++) o[i][jj] *= al[i];

#pragma unroll 2
        for (int kk = 0; kk < 64; kk++) {
            float p[4], v[8];
#pragma unroll
            for (int i = 0; i < 4; i++)  p[i] = sS[(ty4 + i) * 65 + kk];
#pragma unroll
            for (int jj = 0; jj < 8; jj++) v[jj] = sK[kk * 129 + tx8 + jj];
#pragma unroll
            for (int i = 0; i < 4; i++)
#pragma unroll
                for (int jj = 0; jj < 8; jj++) o[i][jj] += p[i] * v[jj];
        }
    }

    float inv[4];
#pragma unroll
    for (int i = 0; i < 4; i++) inv[i] = 1.0f / sL[ty4 + i];

    float* Obase = gO + ((size_t)(b * SEQ + qb * 64)) * DM + h * HD;
#pragma unroll
    for (int i = 0; i < 4; i++) {
        float4 lo = make_float4(o[i][0] * inv[i], o[i][1] * inv[i],
                                o[i][2] * inv[i], o[i][3] * inv[i]);
        float4 hi = make_float4(o[i][4] * inv[i], o[i][5] * inv[i],
                                o[i][6] * inv[i], o[i][7] * inv[i]);
        *(float4*)&Obase[(size_t)(ty4 + i) * DM + tx8]     = lo;
        *(float4*)&Obase[(size_t)(ty4 + i) * DM + tx8 + 4] = hi;
    }
}

// ===========================================================================
extern "C" void kernel_launch(void* const* d_in, const int* in_sizes, int n_in,
                              void* d_out, int out_size)
{
    const float* x   = (const float*)d_in[0];
    const float* Wq  = (const float*)d_in[1];
    const float* Wkv = (const float*)d_in[2];
    const float* Wo  = (const float*)d_in[3];
    float* out = (float*)d_out;

    float *pQ, *pKV, *pO;
    cudaGetSymbolAddress((void**)&pQ,  gQ);
    cudaGetSymbolAddress((void**)&pKV, gKV);
    cudaGetSymbolAddress((void**)&pO,  gO);

    __nv_bfloat16 *xh, *xl, *wqh, *wql, *wkvh, *wkvl, *woh, *wol, *oh, *ol;
    cudaGetSymbolAddress((void**)&xh,  g_xh);   cudaGetSymbolAddress((void**)&xl,  g_xl);
    cudaGetSymbolAddress((void**)&wqh, g_wqh);  cudaGetSymbolAddress((void**)&wql, g_wql);
    cudaGetSymbolAddress((void**)&wkvh, g_wkvh); cudaGetSymbolAddress((void**)&wkvl, g_wkvl);
    cudaGetSymbolAddress((void**)&woh, g_woh);  cudaGetSymbolAddress((void**)&wol, g_wol);
    cudaGetSymbolAddress((void**)&oh,  g_oh);   cudaGetSymbolAddress((void**)&ol,  g_ol);

    cudaFuncSetAttribute(gemm_mma,
                         cudaFuncAttributeMaxDynamicSharedMemorySize, GEMM_SMEM);
    cudaFuncSetAttribute(attn_kernel,
                         cudaFuncAttributeMaxDynamicSharedMemorySize, ATTN_SMEM_BYTES);

    // convert operands to bf16 hi/lo
    {
        int n4 = MTOT * DM / 4;
        cvt_hilo<<<(n4 + 255) / 256, 256>>>((const float4*)x, (uint2*)xh, (uint2*)xl, n4);
        n4 = DM * DM / 4;
        cvt_hilo<<<(n4 + 255) / 256, 256>>>((const float4*)Wq, (uint2*)wqh, (uint2*)wql, n4);
        cvt_hilo<<<(n4 + 255) / 256, 256>>>((const float4*)Wo, (uint2*)woh, (uint2*)wol, n4);
        n4 = KVD * DM / 4;
        cvt_hilo<<<(n4 + 255) / 256, 256>>>((const float4*)Wkv, (uint2*)wkvh, (uint2*)wkvl, n4);
    }

    // Q projection: [4096,2048] = x @ Wq^T
    gemm_mma<<<dim3(DM / 128, MTOT / 128), 256, GEMM_SMEM>>>(xh, xl, wqh, wql, pQ, DM, DM);
    // KV projection: [4096,256] = x @ Wkv^T
    gemm_mma<<<dim3(KVD / 128, MTOT / 128), 256, GEMM_SMEM>>>(xh, xl, wkvh, wkvl, pKV, KVD, DM);
    // Attention (fp32 SIMT)
    attn_kernel<<<dim3(SEQ / 64, BATCH * NH), 256, ATTN_SMEM_BYTES>>>();
    // convert attention output, then O projection
    {
        int n4 = MTOT * DM / 4;
        cvt_hilo<<<(n4 + 255) / 256, 256>>>((const float4*)pO, (uint2*)oh, (uint2*)ol, n4);
    }
    gemm_mma<<<dim3(DM / 128, MTOT / 128), 256, GEMM_SMEM>>>(oh, ol, woh, wol, out, DM, DM);
}

// round 4
// speedup vs baseline: 3.3700x; 2.3426x over previous
#include <cuda_runtime.h>
#include <cuda_bf16.h>
#include <cstdint>

#define BATCH 2
#define SEQ   2048
#define DM    2048
#define NH    16
#define HD    128
#define KVD   256
#define MTOT  (BATCH*SEQ)

// bf16 hi/lo scratch (pre-converted / kernel-produced operands)
__device__ __nv_bfloat16 g_xh[MTOT * DM],  g_xl[MTOT * DM];
__device__ __nv_bfloat16 g_wqh[DM * DM],   g_wql[DM * DM];
__device__ __nv_bfloat16 g_wkvh[KVD * DM], g_wkvl[KVD * DM];
__device__ __nv_bfloat16 g_woh[DM * DM],   g_wol[DM * DM];
__device__ __nv_bfloat16 g_qh[MTOT * DM],  g_ql[MTOT * DM];
__device__ __nv_bfloat16 g_kvh[MTOT * KVD], g_kvl[MTOT * KVD];
__device__ __nv_bfloat16 g_oh[MTOT * DM],  g_ol[MTOT * DM];

// ===========================================================================
// helpers
// ===========================================================================
__device__ __forceinline__ uint32_t smem_u32(const void* p) {
    uint32_t a;
    asm("{ .reg .u64 t; cvta.to.shared.u64 t, %1; cvt.u32.u64 %0, t; }"
        : "=r"(a) : "l"(p));
    return a;
}

#define CP16(dst, src) \
    asm volatile("cp.async.cg.shared.global [%0], [%1], 16;" \
                 :: "r"(dst), "l"(src))
#define CP_COMMIT() asm volatile("cp.async.commit_group;")
#define CP_WAIT(n)  asm volatile("cp.async.wait_group %0;" :: "n"(n))

#define LDSM4(r, addr)                                                        \
    asm volatile("ldmatrix.sync.aligned.m8n8.x4.shared.b16 {%0,%1,%2,%3}, [%4];" \
        : "=r"((r)[0]), "=r"((r)[1]), "=r"((r)[2]), "=r"((r)[3]) : "r"(addr))
#define LDSM2(r, addr)                                                        \
    asm volatile("ldmatrix.sync.aligned.m8n8.x2.shared.b16 {%0,%1}, [%2];"    \
        : "=r"((r)[0]), "=r"((r)[1]) : "r"(addr))
#define LDSM2T(r, addr)                                                       \
    asm volatile("ldmatrix.sync.aligned.m8n8.x2.trans.shared.b16 {%0,%1}, [%2];" \
        : "=r"((r)[0]), "=r"((r)[1]) : "r"(addr))

#define MMA16816(c, a, b)                                                     \
    asm volatile("mma.sync.aligned.m16n8k16.row.col.f32.bf16.bf16.f32 "       \
        "{%0,%1,%2,%3}, {%4,%5,%6,%7}, {%8,%9}, {%0,%1,%2,%3};"               \
        : "+f"((c)[0]), "+f"((c)[1]), "+f"((c)[2]), "+f"((c)[3])              \
        : "r"((a)[0]), "r"((a)[1]), "r"((a)[2]), "r"((a)[3]),                 \
          "r"((b)[0]), "r"((b)[1]))

__device__ __forceinline__ void pack_hilo(float p0, float p1,
                                          uint32_t& hi, uint32_t& lo) {
    __nv_bfloat162 h = __floats2bfloat162_rn(p0, p1);
    __nv_bfloat162 l = __floats2bfloat162_rn(p0 - __bfloat162float(h.x),
                                             p1 - __bfloat162float(h.y));
    hi = *(uint32_t*)&h;
    lo = *(uint32_t*)&l;
}

// ===========================================================================
// fp32 -> bf16 hi/lo conversion (bandwidth-bound pass, inputs only)
// ===========================================================================
__global__ void __launch_bounds__(256)
cvt_hilo(const float4* __restrict__ in, uint2* __restrict__ hi,
         uint2* __restrict__ lo, int n4)
{
    int i = blockIdx.x * blockDim.x + threadIdx.x;
    if (i >= n4) return;
    float4 f = in[i];
    __nv_bfloat162 h0 = __floats2bfloat162_rn(f.x, f.y);
    __nv_bfloat162 h1 = __floats2bfloat162_rn(f.z, f.w);
    __nv_bfloat162 l0 = __floats2bfloat162_rn(f.x - __bfloat162float(h0.x),
                                              f.y - __bfloat162float(h0.y));
    __nv_bfloat162 l1 = __floats2bfloat162_rn(f.z - __bfloat162float(h1.x),
                                              f.w - __bfloat162float(h1.y));
    hi[i] = make_uint2(*(uint32_t*)&h0, *(uint32_t*)&h1);
    lo[i] = make_uint2(*(uint32_t*)&l0, *(uint32_t*)&l1);
}

// ===========================================================================
// bf16x3 mma.sync GEMM: C[M,N] = A[M,K] * B[N,K]^T
// CTA tile 128x128, BK=32, 256 threads (8 warps: 2m x 4n, 64x32 each).
// HILO=true: write C as bf16 hi/lo pair instead of fp32.
// ===========================================================================
#define GSTAGE   40960
#define GBUF     10240
#define GEMM_SMEM (2 * GSTAGE)

template<bool HILO>
__global__ void __launch_bounds__(256, 1)
gemm_mma(const __nv_bfloat16* __restrict__ Ah, const __nv_bfloat16* __restrict__ Al,
         const __nv_bfloat16* __restrict__ Bh, const __nv_bfloat16* __restrict__ Bl,
         float* __restrict__ C,
         __nv_bfloat16* __restrict__ Ch, __nv_bfloat16* __restrict__ Cl,
         int N, int K)
{
    extern __shared__ char smem[];
    const uint32_t sbase = smem_u32(smem);

    const int tid  = threadIdx.x;
    const int lane = tid & 31;
    const int wid  = tid >> 5;
    const int wm   = (wid >> 2) * 64;
    const int wn   = (wid & 3) * 32;
    const int m0   = blockIdx.y * 128;
    const int n0   = blockIdx.x * 128;

    const int lrow = tid >> 1;
    const int lc   = (tid & 1) * 2;

    const __nv_bfloat16* gsrc[4];
    gsrc[0] = Ah + (size_t)(m0 + lrow) * K;
    gsrc[1] = Al + (size_t)(m0 + lrow) * K;
    gsrc[2] = Bh + (size_t)(n0 + lrow) * K;
    gsrc[3] = Bl + (size_t)(n0 + lrow) * K;
    const uint32_t drow = sbase + lrow * 80 + lc * 16;

    float acc[4][4][4] = {};

    const int NIT = K >> 5;

#pragma unroll
    for (int buf = 0; buf < 4; buf++) {
        CP16(drow + buf * GBUF,      gsrc[buf] + lc * 8);
        CP16(drow + buf * GBUF + 16, gsrc[buf] + lc * 8 + 8);
    }
    CP_COMMIT();

    for (int kt = 0; kt < NIT; kt++) {
        if (kt + 1 < NIT) {
            const int kb = (kt + 1) << 5;
            const uint32_t d = drow + ((kt + 1) & 1) * GSTAGE;
#pragma unroll
            for (int buf = 0; buf < 4; buf++) {
                CP16(d + buf * GBUF,      gsrc[buf] + kb + lc * 8);
                CP16(d + buf * GBUF + 16, gsrc[buf] + kb + lc * 8 + 8);
            }
            CP_COMMIT();
            CP_WAIT(1);
        } else {
            CP_WAIT(0);
        }
        __syncthreads();

        const uint32_t sb = sbase + (kt & 1) * GSTAGE;
#pragma unroll
        for (int ks = 0; ks < 2; ks++) {
            uint32_t ah[4][4], al[4][4], bh[4][2], bl[4][2];
#pragma unroll
            for (int mi = 0; mi < 4; mi++) {
                uint32_t aaddr = sb + (wm + mi * 16 + (lane & 15)) * 80
                               + ks * 32 + (lane >> 4) * 16;
                LDSM4(ah[mi], aaddr);
                LDSM4(al[mi], aaddr + GBUF);
            }
#pragma unroll
            for (int ni = 0; ni < 4; ni++) {
                uint32_t baddr = sb + 2 * GBUF + (wn + ni * 8 + (lane & 7)) * 80
                               + ks * 32 + ((lane >> 3) & 1) * 16;
                LDSM2(bh[ni], baddr);
                LDSM2(bl[ni], baddr + GBUF);
            }
#pragma unroll
            for (int mi = 0; mi < 4; mi++)
#pragma unroll
                for (int ni = 0; ni < 4; ni++) {
                    MMA16816(acc[mi][ni], ah[mi], bh[ni]);
                    MMA16816(acc[mi][ni], ah[mi], bl[ni]);
                    MMA16816(acc[mi][ni], al[mi], bh[ni]);
                }
        }
        __syncthreads();
    }

    const int rg = lane >> 2;
    const int cg = (lane & 3) * 2;
#pragma unroll
    for (int mi = 0; mi < 4; mi++) {
#pragma unroll
        for (int ni = 0; ni < 4; ni++) {
            int r = m0 + wm + mi * 16 + rg;
            int c = n0 + wn + ni * 8 + cg;
            if (HILO) {
                uint32_t h0, l0, h1, l1;
                pack_hilo(acc[mi][ni][0], acc[mi][ni][1], h0, l0);
                pack_hilo(acc[mi][ni][2], acc[mi][ni][3], h1, l1);
                *(uint32_t*)&Ch[(size_t)r * N + c]       = h0;
                *(uint32_t*)&Cl[(size_t)r * N + c]       = l0;
                *(uint32_t*)&Ch[(size_t)(r + 8) * N + c] = h1;
                *(uint32_t*)&Cl[(size_t)(r + 8) * N + c] = l1;
            } else {
                *(float2*)&C[(size_t)r * N + c] =
                    make_float2(acc[mi][ni][0], acc[mi][ni][1]);
                *(float2*)&C[(size_t)(r + 8) * N + c] =
                    make_float2(acc[mi][ni][2], acc[mi][ni][3]);
            }
        }
    }
}

// ===========================================================================
// mma.sync flash attention, causal MQA, bf16x3.
// BM=128 (8 warps x 16 rows), BN=64. Q persistent in smem; K/V double-buffered.
// Row stride 272B (256 data + 16 pad) -> conflict-free ldmatrix.
// ===========================================================================
#define AT_STRIDE 272
#define AT_QSZ    34816            // 128 rows * 272
#define AT_KVBUF  17408            // 64 rows * 272
#define AT_STAGE  (4 * AT_KVBUF)   // Khi,Klo,Vhi,Vlo
#define AT_KV0    (2 * AT_QSZ)     // after Qhi,Qlo
#define ATTN_SMEM (2 * AT_QSZ + 2 * AT_STAGE)   // 208,896 B
#define CSC 0.12751727652f         // (1/sqrt(128)) * log2(e)

__device__ __forceinline__ void attn_kv_load(uint32_t sb, int st, int tile,
                                             int b, int tid)
{
    const int base = b * SEQ + tile * 64;
    const uint32_t kb = sb + AT_KV0 + st * AT_STAGE;
#pragma unroll
    for (int i = 0; i < 4; i++) {
        int c = tid + i * 256;
        int row = c >> 4;
        int c16 = c & 15;
        uint32_t dst = kb + row * AT_STRIDE + c16 * 16;
        size_t src = (size_t)(base + row) * KVD + c16 * 8;
        CP16(dst,                 g_kvh + src);          // Khi
        CP16(dst + AT_KVBUF,      g_kvl + src);          // Klo
        CP16(dst + 2 * AT_KVBUF,  g_kvh + src + 128);    // Vhi
        CP16(dst + 3 * AT_KVBUF,  g_kvl + src + 128);    // Vlo
    }
}

__global__ void __launch_bounds__(256, 1)
attn_mma()
{
    extern __shared__ char smem[];
    const uint32_t sb = smem_u32(smem);

    const int tid  = threadIdx.x;
    const int lane = tid & 31;
    const int w    = tid >> 5;
    const int qb   = (int)gridDim.x - 1 - (int)blockIdx.x;  // heavy blocks first
    const int b    = blockIdx.y >> 4;
    const int h    = blockIdx.y & 15;
    const int rg   = lane >> 2;
    const int qc   = lane & 3;

    // ---- stage Q hi/lo (persistent) ----
#pragma unroll
    for (int i = 0; i < 8; i++) {
        int c = tid + i * 256;
        int row = c >> 4;
        int c16 = c & 15;
        uint32_t dst = sb + row * AT_STRIDE + c16 * 16;
        size_t src = (size_t)(b * SEQ + qb * 128 + row) * DM + h * HD + c16 * 8;
        CP16(dst,           g_qh + src);
        CP16(dst + AT_QSZ,  g_ql + src);
    }
    CP_COMMIT();

    const int jmax = 2 * qb + 1;
    attn_kv_load(sb, 0, 0, b, tid);
    CP_COMMIT();

    float o[16][4] = {};
    float m0 = -1e30f, m1 = -1e30f, l0 = 0.0f, l1 = 0.0f;

    for (int j = 0; j <= jmax; j++) {
        if (j < jmax) {
            attn_kv_load(sb, (j + 1) & 1, j + 1, b, tid);
            CP_COMMIT();
            CP_WAIT(1);
        } else {
            CP_WAIT(0);
        }
        __syncthreads();

        const uint32_t kvb = sb + AT_KV0 + (j & 1) * AT_STAGE;

        // ---- S = Q K^T (x3), accum fp32 ----
        float s[8][4] = {};
#pragma unroll
        for (int ks = 0; ks < 8; ks++) {
            uint32_t qh4[4], ql4[4];
            uint32_t qaddr = sb + (w * 16 + (lane & 15)) * AT_STRIDE
                           + ks * 32 + (lane >> 4) * 16;
            LDSM4(qh4, qaddr);
            LDSM4(ql4, qaddr + AT_QSZ);
#pragma unroll
            for (int nt = 0; nt < 8; nt++) {
                uint32_t kh2[2], kl2[2];
                uint32_t kaddr = kvb + (nt * 8 + (lane & 7)) * AT_STRIDE
                               + ks * 32 + ((lane >> 3) & 1) * 16;
                LDSM2(kh2, kaddr);
                LDSM2(kl2, kaddr + AT_KVBUF);
                MMA16816(s[nt], qh4, kh2);
                MMA16816(s[nt], qh4, kl2);
                MMA16816(s[nt], ql4, kh2);
            }
        }

        // ---- causal mask (diagonal tiles only) ----
        if (j >= 2 * qb) {
            const int rbase = qb * 128 + w * 16 + rg;
            const int cbase = j * 64 + qc * 2;
#pragma unroll
            for (int nt = 0; nt < 8; nt++) {
                int c0 = cbase + nt * 8;
                if (c0 > rbase)          s[nt][0] = -1e30f;
                if (c0 + 1 > rbase)      s[nt][1] = -1e30f;
                if (c0 > rbase + 8)      s[nt][2] = -1e30f;
                if (c0 + 1 > rbase + 8)  s[nt][3] = -1e30f;
            }
        }

        // ---- online softmax (register, quad-reduced) ----
        float mt0 = -1e30f, mt1 = -1e30f;
#pragma unroll
        for (int nt = 0; nt < 8; nt++) {
            mt0 = fmaxf(mt0, fmaxf(s[nt][0], s[nt][1]));
            mt1 = fmaxf(mt1, fmaxf(s[nt][2], s[nt][3]));
        }
        mt0 = fmaxf(mt0, __shfl_xor_sync(0xffffffff, mt0, 1));
        mt0 = fmaxf(mt0, __shfl_xor_sync(0xffffffff, mt0, 2));
        mt1 = fmaxf(mt1, __shfl_xor_sync(0xffffffff, mt1, 1));
        mt1 = fmaxf(mt1, __shfl_xor_sync(0xffffffff, mt1, 2));

        float m0n = fmaxf(m0, mt0), m1n = fmaxf(m1, mt1);
        float a0 = exp2f((m0 - m0n) * CSC);
        float a1 = exp2f((m1 - m1n) * CSC);

        float ls0 = 0.0f, ls1 = 0.0f;
#pragma unroll
        for (int nt = 0; nt < 8; nt++) {
            s[nt][0] = exp2f((s[nt][0] - m0n) * CSC);
            s[nt][1] = exp2f((s[nt][1] - m0n) * CSC);
            s[nt][2] = exp2f((s[nt][2] - m1n) * CSC);
            s[nt][3] = exp2f((s[nt][3] - m1n) * CSC);
            ls0 += s[nt][0] + s[nt][1];
            ls1 += s[nt][2] + s[nt][3];
        }
        ls0 += __shfl_xor_sync(0xffffffff, ls0, 1);
        ls0 += __shfl_xor_sync(0xffffffff, ls0, 2);
        ls1 += __shfl_xor_sync(0xffffffff, ls1, 1);
        ls1 += __shfl_xor_sync(0xffffffff, ls1, 2);

        l0 = l0 * a0 + ls0;
        l1 = l1 * a1 + ls1;
        m0 = m0n; m1 = m1n;

#pragma unroll
        for (int nt2 = 0; nt2 < 16; nt2++) {
            o[nt2][0] *= a0; o[nt2][1] *= a0;
            o[nt2][2] *= a1; o[nt2][3] *= a1;
        }

        // ---- O += P V (x3) ----
#pragma unroll
        for (int kk = 0; kk < 4; kk++) {
            uint32_t ahi[4], alo[4];
            pack_hilo(s[2*kk][0],   s[2*kk][1],   ahi[0], alo[0]);
            pack_hilo(s[2*kk][2],   s[2*kk][3],   ahi[1], alo[1]);
            pack_hilo(s[2*kk+1][0], s[2*kk+1][1], ahi[2], alo[2]);
            pack_hilo(s[2*kk+1][2], s[2*kk+1][3], ahi[3], alo[3]);
#pragma unroll
            for (int nt2 = 0; nt2 < 16; nt2++) {
                uint32_t vh2[2], vl2[2];
                uint32_t vaddr = kvb + 2 * AT_KVBUF
                               + (kk * 16 + (lane & 15)) * AT_STRIDE + nt2 * 16;
                LDSM2T(vh2, vaddr);
                LDSM2T(vl2, vaddr + AT_KVBUF);
                MMA16816(o[nt2], ahi, vh2);
                MMA16816(o[nt2], ahi, vl2);
                MMA16816(o[nt2], alo, vh2);
            }
        }
        __syncthreads();
    }

    // ---- normalize, write bf16 hi/lo ----
    const float inv0 = 1.0f / l0;
    const float inv1 = 1.0f / l1;
    const size_t row0 = (size_t)(b * SEQ + qb * 128 + w * 16 + rg) * DM;
    const size_t row1 = row0 + 8 * DM;
#pragma unroll
    for (int nt2 = 0; nt2 < 16; nt2++) {
        int col = h * HD + nt2 * 8 + qc * 2;
        uint32_t h0, l0w, h1, l1w;
        pack_hilo(o[nt2][0] * inv0, o[nt2][1] * inv0, h0, l0w);
        pack_hilo(o[nt2][2] * inv1, o[nt2][3] * inv1, h1, l1w);
        *(uint32_t*)&g_oh[row0 + col] = h0;
        *(uint32_t*)&g_ol[row0 + col] = l0w;
        *(uint32_t*)&g_oh[row1 + col] = h1;
        *(uint32_t*)&g_ol[row1 + col] = l1w;
    }
}

// ===========================================================================
extern "C" void kernel_launch(void* const* d_in, const int* in_sizes, int n_in,
                              void* d_out, int out_size)
{
    const float* x   = (const float*)d_in[0];
    const float* Wq  = (const float*)d_in[1];
    const float* Wkv = (const float*)d_in[2];
    const float* Wo  = (const float*)d_in[3];
    float* out = (float*)d_out;

    __nv_bfloat16 *xh, *xl, *wqh, *wql, *wkvh, *wkvl, *woh, *wol;
    __nv_bfloat16 *qh, *ql, *kvh, *kvl, *oh, *ol;
    cudaGetSymbolAddress((void**)&xh,  g_xh);   cudaGetSymbolAddress((void**)&xl,  g_xl);
    cudaGetSymbolAddress((void**)&wqh, g_wqh);  cudaGetSymbolAddress((void**)&wql, g_wql);
    cudaGetSymbolAddress((void**)&wkvh, g_wkvh); cudaGetSymbolAddress((void**)&wkvl, g_wkvl);
    cudaGetSymbolAddress((void**)&woh, g_woh);  cudaGetSymbolAddress((void**)&wol, g_wol);
    cudaGetSymbolAddress((void**)&qh,  g_qh);   cudaGetSymbolAddress((void**)&ql,  g_ql);
    cudaGetSymbolAddress((void**)&kvh, g_kvh);  cudaGetSymbolAddress((void**)&kvl, g_kvl);
    cudaGetSymbolAddress((void**)&oh,  g_oh);   cudaGetSymbolAddress((void**)&ol,  g_ol);

    cudaFuncSetAttribute(gemm_mma<false>,
                         cudaFuncAttributeMaxDynamicSharedMemorySize, GEMM_SMEM);
    cudaFuncSetAttribute(gemm_mma<true>,
                         cudaFuncAttributeMaxDynamicSharedMemorySize, GEMM_SMEM);
    cudaFuncSetAttribute(attn_mma,
                         cudaFuncAttributeMaxDynamicSharedMemorySize, ATTN_SMEM);

    // convert fp32 inputs to bf16 hi/lo
    {
        int n4 = MTOT * DM / 4;
        cvt_hilo<<<(n4 + 255) / 256, 256>>>((const float4*)x, (uint2*)xh, (uint2*)xl, n4);
        n4 = DM * DM / 4;
        cvt_hilo<<<(n4 + 255) / 256, 256>>>((const float4*)Wq, (uint2*)wqh, (uint2*)wql, n4);
        cvt_hilo<<<(n4 + 255) / 256, 256>>>((const float4*)Wo, (uint2*)woh, (uint2*)wol, n4);
        n4 = KVD * DM / 4;
        cvt_hilo<<<(n4 + 255) / 256, 256>>>((const float4*)Wkv, (uint2*)wkvh, (uint2*)wkvl, n4);
    }

    // Q projection -> bf16 hi/lo directly
    gemm_mma<true><<<dim3(DM / 128, MTOT / 128), 256, GEMM_SMEM>>>(
        xh, xl, wqh, wql, nullptr, qh, ql, DM, DM);
    // KV projection -> bf16 hi/lo directly
    gemm_mma<true><<<dim3(KVD / 128, MTOT / 128), 256, GEMM_SMEM>>>(
        xh, xl, wkvh, wkvl, nullptr, kvh, kvl, KVD, DM);
    // Attention (tensor-core, bf16x3) -> bf16 hi/lo
    attn_mma<<<dim3(SEQ / 128, BATCH * NH), 256, ATTN_SMEM>>>();
    // O projection -> fp32 output
    gemm_mma<false><<<dim3(DM / 128, MTOT / 128), 256, GEMM_SMEM>>>(
        oh, ol, woh, wol, out, nullptr, nullptr, DM, DM);
}

// round 5
// speedup vs baseline: 7.0344x; 2.0874x over previous
#include <cuda_runtime.h>
#include <cuda_fp16.h>
#include <cstdint>

#define BATCH 2
#define SEQ   2048
#define DM    2048
#define NH    16
#define HD    128
#define KVD   256
#define MTOT  (BATCH*SEQ)

// fp16 scratch
__device__ __half g_xh[MTOT * DM];
__device__ __half g_wqh[DM * DM];
__device__ __half g_wkvh[KVD * DM];
__device__ __half g_woh[DM * DM];
__device__ __half g_qh[MTOT * DM];
__device__ __half g_kvh[MTOT * KVD];
__device__ __half g_oh[MTOT * DM];

// ===========================================================================
// helpers
// ===========================================================================
__device__ __forceinline__ uint32_t smem_u32(const void* p) {
    uint32_t a;
    asm("{ .reg .u64 t; cvta.to.shared.u64 t, %1; cvt.u32.u64 %0, t; }"
        : "=r"(a) : "l"(p));
    return a;
}

#define CP16(dst, src) \
    asm volatile("cp.async.cg.shared.global [%0], [%1], 16;" \
                 :: "r"(dst), "l"(src))
#define CP_COMMIT() asm volatile("cp.async.commit_group;")
#define CP_WAIT(n)  asm volatile("cp.async.wait_group %0;" :: "n"(n))

#define LDSM4(r, addr)                                                        \
    asm volatile("ldmatrix.sync.aligned.m8n8.x4.shared.b16 {%0,%1,%2,%3}, [%4];" \
        : "=r"((r)[0]), "=r"((r)[1]), "=r"((r)[2]), "=r"((r)[3]) : "r"(addr))
#define LDSM4T(r, addr)                                                       \
    asm volatile("ldmatrix.sync.aligned.m8n8.x4.trans.shared.b16 {%0,%1,%2,%3}, [%4];" \
        : "=r"((r)[0]), "=r"((r)[1]), "=r"((r)[2]), "=r"((r)[3]) : "r"(addr))

#define MMAF16(c, a, b)                                                       \
    asm volatile("mma.sync.aligned.m16n8k16.row.col.f32.f16.f16.f32 "         \
        "{%0,%1,%2,%3}, {%4,%5,%6,%7}, {%8,%9}, {%0,%1,%2,%3};"               \
        : "+f"((c)[0]), "+f"((c)[1]), "+f"((c)[2]), "+f"((c)[3])              \
        : "r"((a)[0]), "r"((a)[1]), "r"((a)[2]), "r"((a)[3]),                 \
          "r"((b)[0]), "r"((b)[1]))

__device__ __forceinline__ uint32_t pack_h2(float a, float b) {
    __half2 h = __floats2half2_rn(a, b);
    return *(uint32_t*)&h;
}

// ===========================================================================
// fp32 -> fp16 conversion (bandwidth-bound pass)
// ===========================================================================
__global__ void __launch_bounds__(256)
cvt_f16(const float4* __restrict__ in, uint2* __restrict__ out, int n4)
{
    int i = blockIdx.x * blockDim.x + threadIdx.x;
    if (i >= n4) return;
    float4 f = in[i];
    out[i] = make_uint2(pack_h2(f.x, f.y), pack_h2(f.z, f.w));
}

// ===========================================================================
// fp16 mma.sync GEMM: C[M,N] = A[M,K] * B[N,K]^T
// CTA tile 128x128, BK=32, 256 threads (8 warps: 2m x 4n, 64x32 each).
// F16OUT: write C as fp16 instead of fp32.
// ===========================================================================
#define GBUF     10240              // 128 rows * 80B
#define GSTAGE   (2 * GBUF)         // A + B
#define GEMM_SMEM (2 * GSTAGE)

template<bool F16OUT>
__global__ void __launch_bounds__(256, 1)
gemm_mma(const __half* __restrict__ Ah, const __half* __restrict__ Bh,
         float* __restrict__ C, __half* __restrict__ Ch, int N, int K)
{
    extern __shared__ char smem[];
    const uint32_t sbase = smem_u32(smem);

    const int tid  = threadIdx.x;
    const int lane = tid & 31;
    const int wid  = tid >> 5;
    const int wm   = (wid >> 2) * 64;
    const int wn   = (wid & 3) * 32;
    const int m0   = blockIdx.y * 128;
    const int n0   = blockIdx.x * 128;

    const int lrow = tid >> 1;            // 0..127
    const int lc   = (tid & 1) * 2;       // chunk 0 or 2

    const __half* gA = Ah + (size_t)(m0 + lrow) * K + lc * 8;
    const __half* gB = Bh + (size_t)(n0 + lrow) * K + lc * 8;
    const uint32_t drow = sbase + lrow * 80 + lc * 16;

    float acc[4][4][4] = {};

    const int NIT = K >> 5;

    CP16(drow,               gA);
    CP16(drow + 16,          gA + 8);
    CP16(drow + GBUF,        gB);
    CP16(drow + GBUF + 16,   gB + 8);
    CP_COMMIT();

    for (int kt = 0; kt < NIT; kt++) {
        if (kt + 1 < NIT) {
            const int kb = (kt + 1) << 5;
            const uint32_t d = drow + ((kt + 1) & 1) * GSTAGE;
            CP16(d,              gA + kb);
            CP16(d + 16,         gA + kb + 8);
            CP16(d + GBUF,       gB + kb);
            CP16(d + GBUF + 16,  gB + kb + 8);
            CP_COMMIT();
            CP_WAIT(1);
        } else {
            CP_WAIT(0);
        }
        __syncthreads();

        const uint32_t sb = sbase + (kt & 1) * GSTAGE;
#pragma unroll
        for (int ks = 0; ks < 2; ks++) {
            uint32_t a4[4][4], b2[4][2];
#pragma unroll
            for (int mi = 0; mi < 4; mi++) {
                uint32_t aaddr = sb + (wm + mi * 16 + (lane & 15)) * 80
                               + ks * 32 + (lane >> 4) * 16;
                LDSM4(a4[mi], aaddr);
            }
#pragma unroll
            for (int np = 0; np < 2; np++) {   // pairs of n8 tiles
                uint32_t r[4];
                uint32_t baddr = sb + GBUF
                               + (wn + np * 16 + ((lane >> 4) << 3) + (lane & 7)) * 80
                               + ks * 32 + ((lane >> 3) & 1) * 16;
                LDSM4(r, baddr);
                b2[np * 2][0]     = r[0]; b2[np * 2][1]     = r[1];
                b2[np * 2 + 1][0] = r[2]; b2[np * 2 + 1][1] = r[3];
            }
#pragma unroll
            for (int mi = 0; mi < 4; mi++)
#pragma unroll
                for (int ni = 0; ni < 4; ni++)
                    MMAF16(acc[mi][ni], a4[mi], b2[ni]);
        }
        __syncthreads();
    }

    const int rg = lane >> 2;
    const int cg = (lane & 3) * 2;
#pragma unroll
    for (int mi = 0; mi < 4; mi++) {
#pragma unroll
        for (int ni = 0; ni < 4; ni++) {
            int r = m0 + wm + mi * 16 + rg;
            int c = n0 + wn + ni * 8 + cg;
            if (F16OUT) {
                *(uint32_t*)&Ch[(size_t)r * N + c] =
                    pack_h2(acc[mi][ni][0], acc[mi][ni][1]);
                *(uint32_t*)&Ch[(size_t)(r + 8) * N + c] =
                    pack_h2(acc[mi][ni][2], acc[mi][ni][3]);
            } else {
                *(float2*)&C[(size_t)r * N + c] =
                    make_float2(acc[mi][ni][0], acc[mi][ni][1]);
                *(float2*)&C[(size_t)(r + 8) * N + c] =
                    make_float2(acc[mi][ni][2], acc[mi][ni][3]);
            }
        }
    }
}

// ===========================================================================
// mma.sync flash attention, causal MQA, fp16.
// BM=128 (8 warps x 16 rows), BN=64. Q persistent; K/V double-buffered.
// Row stride 272B (256 data + 16 pad).
// ===========================================================================
#define AT_STRIDE 272
#define AT_QSZ    34816            // 128 * 272
#define AT_KVBUF  17408            // 64 * 272
#define AT_STAGE  (2 * AT_KVBUF)   // K, V
#define AT_KV0    AT_QSZ
#define ATTN_SMEM (AT_QSZ + 2 * AT_STAGE)   // 104,448 B
#define CSC 0.12751727652f         // (1/sqrt(128)) * log2(e)

__device__ __forceinline__ void attn_kv_load(uint32_t sb, int st, int tile,
                                             int b, int tid)
{
    const int base = b * SEQ + tile * 64;
    const uint32_t kb = sb + AT_KV0 + st * AT_STAGE;
#pragma unroll
    for (int i = 0; i < 4; i++) {
        int c = tid + i * 256;
        int row = c >> 4;
        int c16 = c & 15;
        uint32_t dst = kb + row * AT_STRIDE + c16 * 16;
        size_t src = (size_t)(base + row) * KVD + c16 * 8;
        CP16(dst,            g_kvh + src);          // K
        CP16(dst + AT_KVBUF, g_kvh + src + 128);    // V
    }
}

__global__ void __launch_bounds__(256, 1)
attn_mma()
{
    extern __shared__ char smem[];
    const uint32_t sb = smem_u32(smem);

    const int tid  = threadIdx.x;
    const int lane = tid & 31;
    const int w    = tid >> 5;
    const int qb   = (int)gridDim.x - 1 - (int)blockIdx.x;  // heavy first
    const int b    = blockIdx.y >> 4;
    const int h    = blockIdx.y & 15;
    const int rg   = lane >> 2;
    const int qc   = lane & 3;

    // stage Q (persistent)
#pragma unroll
    for (int i = 0; i < 8; i++) {
        int c = tid + i * 256;
        int row = c >> 4;
        int c16 = c & 15;
        size_t src = (size_t)(b * SEQ + qb * 128 + row) * DM + h * HD + c16 * 8;
        CP16(sb + row * AT_STRIDE + c16 * 16, g_qh + src);
    }
    CP_COMMIT();

    const int jmax = 2 * qb + 1;
    attn_kv_load(sb, 0, 0, b, tid);
    CP_COMMIT();

    float o[16][4] = {};
    float m0 = -1e30f, m1 = -1e30f, l0 = 0.0f, l1 = 0.0f;

    for (int j = 0; j <= jmax; j++) {
        if (j < jmax) {
            attn_kv_load(sb, (j + 1) & 1, j + 1, b, tid);
            CP_COMMIT();
            CP_WAIT(1);
        } else {
            CP_WAIT(0);
        }
        __syncthreads();

        const uint32_t kvb = sb + AT_KV0 + (j & 1) * AT_STAGE;

        // ---- S = Q K^T ----
        float s[8][4] = {};
#pragma unroll
        for (int ks = 0; ks < 8; ks++) {
            uint32_t q4[4];
            uint32_t qaddr = sb + (w * 16 + (lane & 15)) * AT_STRIDE
                           + ks * 32 + (lane >> 4) * 16;
            LDSM4(q4, qaddr);
#pragma unroll
            for (int np = 0; np < 4; np++) {     // pairs of n8 tiles
                uint32_t r[4];
                uint32_t kaddr = kvb
                               + (np * 16 + ((lane >> 4) << 3) + (lane & 7)) * AT_STRIDE
                               + ks * 32 + ((lane >> 3) & 1) * 16;
                LDSM4(r, kaddr);
                uint32_t b0[2] = { r[0], r[1] };
                uint32_t b1[2] = { r[2], r[3] };
                MMAF16(s[np * 2],     q4, b0);
                MMAF16(s[np * 2 + 1], q4, b1);
            }
        }

        // ---- causal mask (diagonal tiles only) ----
        if (j >= 2 * qb) {
            const int rbase = qb * 128 + w * 16 + rg;
            const int cbase = j * 64 + qc * 2;
#pragma unroll
            for (int nt = 0; nt < 8; nt++) {
                int c0 = cbase + nt * 8;
                if (c0 > rbase)          s[nt][0] = -1e30f;
                if (c0 + 1 > rbase)      s[nt][1] = -1e30f;
                if (c0 > rbase + 8)      s[nt][2] = -1e30f;
                if (c0 + 1 > rbase + 8)  s[nt][3] = -1e30f;
            }
        }

        // ---- online softmax ----
        float mt0 = -1e30f, mt1 = -1e30f;
#pragma unroll
        for (int nt = 0; nt < 8; nt++) {
            mt0 = fmaxf(mt0, fmaxf(s[nt][0], s[nt][1]));
            mt1 = fmaxf(mt1, fmaxf(s[nt][2], s[nt][3]));
        }
        mt0 = fmaxf(mt0, __shfl_xor_sync(0xffffffff, mt0, 1));
        mt0 = fmaxf(mt0, __shfl_xor_sync(0xffffffff, mt0, 2));
        mt1 = fmaxf(mt1, __shfl_xor_sync(0xffffffff, mt1, 1));
        mt1 = fmaxf(mt1, __shfl_xor_sync(0xffffffff, mt1, 2));

        float m0n = fmaxf(m0, mt0), m1n = fmaxf(m1, mt1);
        float a0 = exp2f((m0 - m0n) * CSC);
        float a1 = exp2f((m1 - m1n) * CSC);

        float ls0 = 0.0f, ls1 = 0.0f;
#pragma unroll
        for (int nt = 0; nt < 8; nt++) {
            s[nt][0] = exp2f((s[nt][0] - m0n) * CSC);
            s[nt][1] = exp2f((s[nt][1] - m0n) * CSC);
            s[nt][2] = exp2f((s[nt][2] - m1n) * CSC);
            s[nt][3] = exp2f((s[nt][3] - m1n) * CSC);
            ls0 += s[nt][0] + s[nt][1];
            ls1 += s[nt][2] + s[nt][3];
        }
        ls0 += __shfl_xor_sync(0xffffffff, ls0, 1);
        ls0 += __shfl_xor_sync(0xffffffff, ls0, 2);
        ls1 += __shfl_xor_sync(0xffffffff, ls1, 1);
        ls1 += __shfl_xor_sync(0xffffffff, ls1, 2);

        l0 = l0 * a0 + ls0;
        l1 = l1 * a1 + ls1;
        m0 = m0n; m1 = m1n;

#pragma unroll
        for (int nt2 = 0; nt2 < 16; nt2++) {
            o[nt2][0] *= a0; o[nt2][1] *= a0;
            o[nt2][2] *= a1; o[nt2][3] *= a1;
        }

        // ---- O += P V ----
#pragma unroll
        for (int kk = 0; kk < 4; kk++) {
            uint32_t p4[4];
            p4[0] = pack_h2(s[2*kk][0],   s[2*kk][1]);
            p4[1] = pack_h2(s[2*kk][2],   s[2*kk][3]);
            p4[2] = pack_h2(s[2*kk+1][0], s[2*kk+1][1]);
            p4[3] = pack_h2(s[2*kk+1][2], s[2*kk+1][3]);
#pragma unroll
            for (int np = 0; np < 8; np++) {     // pairs of n8 output tiles
                uint32_t r[4];
                uint32_t vaddr = kvb + AT_KVBUF
                               + (kk * 16 + (lane & 15)) * AT_STRIDE
                               + (np * 2 + (lane >> 4)) * 16;
                LDSM4T(r, vaddr);
                uint32_t v0[2] = { r[0], r[1] };
                uint32_t v1[2] = { r[2], r[3] };
                MMAF16(o[np * 2],     p4, v0);
                MMAF16(o[np * 2 + 1], p4, v1);
            }
        }
        __syncthreads();
    }

    // ---- normalize, write fp16 ----
    const float inv0 = 1.0f / l0;
    const float inv1 = 1.0f / l1;
    const size_t row0 = (size_t)(b * SEQ + qb * 128 + w * 16 + rg) * DM;
    const size_t row1 = row0 + 8 * DM;
#pragma unroll
    for (int nt2 = 0; nt2 < 16; nt2++) {
        int col = h * HD + nt2 * 8 + qc * 2;
        *(uint32_t*)&g_oh[row0 + col] = pack_h2(o[nt2][0] * inv0, o[nt2][1] * inv0);
        *(uint32_t*)&g_oh[row1 + col] = pack_h2(o[nt2][2] * inv1, o[nt2][3] * inv1);
    }
}

// ===========================================================================
extern "C" void kernel_launch(void* const* d_in, const int* in_sizes, int n_in,
                              void* d_out, int out_size)
{
    const float* x   = (const float*)d_in[0];
    const float* Wq  = (const float*)d_in[1];
    const float* Wkv = (const float*)d_in[2];
    const float* Wo  = (const float*)d_in[3];
    float* out = (float*)d_out;

    __half *xh, *wqh, *wkvh, *woh, *qh, *kvh, *oh;
    cudaGetSymbolAddress((void**)&xh,   g_xh);
    cudaGetSymbolAddress((void**)&wqh,  g_wqh);
    cudaGetSymbolAddress((void**)&wkvh, g_wkvh);
    cudaGetSymbolAddress((void**)&woh,  g_woh);
    cudaGetSymbolAddress((void**)&qh,   g_qh);
    cudaGetSymbolAddress((void**)&kvh,  g_kvh);
    cudaGetSymbolAddress((void**)&oh,   g_oh);

    cudaFuncSetAttribute(gemm_mma<false>,
                         cudaFuncAttributeMaxDynamicSharedMemorySize, GEMM_SMEM);
    cudaFuncSetAttribute(gemm_mma<true>,
                         cudaFuncAttributeMaxDynamicSharedMemorySize, GEMM_SMEM);
    cudaFuncSetAttribute(attn_mma,
                         cudaFuncAttributeMaxDynamicSharedMemorySize, ATTN_SMEM);

    // convert fp32 inputs to fp16
    {
        int n4 = MTOT * DM / 4;
        cvt_f16<<<(n4 + 255) / 256, 256>>>((const float4*)x, (uint2*)xh, n4);
        n4 = DM * DM / 4;
        cvt_f16<<<(n4 + 255) / 256, 256>>>((const float4*)Wq, (uint2*)wqh, n4);
        cvt_f16<<<(n4 + 255) / 256, 256>>>((const float4*)Wo, (uint2*)woh, n4);
        n4 = KVD * DM / 4;
        cvt_f16<<<(n4 + 255) / 256, 256>>>((const float4*)Wkv, (uint2*)wkvh, n4);
    }

    // Q projection -> fp16
    gemm_mma<true><<<dim3(DM / 128, MTOT / 128), 256, GEMM_SMEM>>>(
        xh, wqh, nullptr, qh, DM, DM);
    // KV projection -> fp16
    gemm_mma<true><<<dim3(KVD / 128, MTOT / 128), 256, GEMM_SMEM>>>(
        xh, wkvh, nullptr, kvh, KVD, DM);
    // Attention (tensor-core fp16) -> fp16
    attn_mma<<<dim3(SEQ / 128, BATCH * NH), 256, ATTN_SMEM>>>();
    // O projection -> fp32 output
    gemm_mma<false><<<dim3(DM / 128, MTOT / 128), 256, GEMM_SMEM>>>(
        oh, woh, out, nullptr, DM, DM);
}

// round 6
// speedup vs baseline: 8.9221x; 1.2683x over previous
#include <cuda_runtime.h>
#include <cuda_fp16.h>
#include <cstdint>

#define BATCH 2
#define SEQ   2048
#define DM    2048
#define NH    16
#define HD    128
#define KVD   256
#define QKVN  (DM + KVD)           // 2304 merged projection width
#define MTOT  (BATCH*SEQ)

// fp16 scratch
__device__ __half g_xh[MTOT * DM];
__device__ __half g_wqkv[QKVN * DM];    // [Wq rows; Wkv rows]
__device__ __half g_woh[DM * DM];
__device__ __half g_qkv[MTOT * QKVN];   // Q cols [0,2048), K [2048,2176), V [2176,2304)
__device__ __half g_oh[MTOT * DM];

// ===========================================================================
// helpers
// ===========================================================================
__device__ __forceinline__ uint32_t smem_u32(const void* p) {
    uint32_t a;
    asm("{ .reg .u64 t; cvta.to.shared.u64 t, %1; cvt.u32.u64 %0, t; }"
        : "=r"(a) : "l"(p));
    return a;
}

#define CP16(dst, src) \
    asm volatile("cp.async.cg.shared.global [%0], [%1], 16;" \
                 :: "r"(dst), "l"(src))
#define CP_COMMIT() asm volatile("cp.async.commit_group;")
#define CP_WAIT(n)  asm volatile("cp.async.wait_group %0;" :: "n"(n))

#define LDSM4(r, addr)                                                        \
    asm volatile("ldmatrix.sync.aligned.m8n8.x4.shared.b16 {%0,%1,%2,%3}, [%4];" \
        : "=r"((r)[0]), "=r"((r)[1]), "=r"((r)[2]), "=r"((r)[3]) : "r"(addr))
#define LDSM4T(r, addr)                                                       \
    asm volatile("ldmatrix.sync.aligned.m8n8.x4.trans.shared.b16 {%0,%1,%2,%3}, [%4];" \
        : "=r"((r)[0]), "=r"((r)[1]), "=r"((r)[2]), "=r"((r)[3]) : "r"(addr))

#define MMAF16(c, a, b)                                                       \
    asm volatile("mma.sync.aligned.m16n8k16.row.col.f32.f16.f16.f32 "         \
        "{%0,%1,%2,%3}, {%4,%5,%6,%7}, {%8,%9}, {%0,%1,%2,%3};"               \
        : "+f"((c)[0]), "+f"((c)[1]), "+f"((c)[2]), "+f"((c)[3])              \
        : "r"((a)[0]), "r"((a)[1]), "r"((a)[2]), "r"((a)[3]),                 \
          "r"((b)[0]), "r"((b)[1]))

__device__ __forceinline__ uint32_t pack_h2(float a, float b) {
    __half2 h = __floats2half2_rn(a, b);
    return *(uint32_t*)&h;
}

// ===========================================================================
// fp32 -> fp16 conversion
// ===========================================================================
__global__ void __launch_bounds__(256)
cvt_f16(const float4* __restrict__ in, uint2* __restrict__ out, int n4)
{
    int i = blockIdx.x * blockDim.x + threadIdx.x;
    if (i >= n4) return;
    float4 f = in[i];
    out[i] = make_uint2(pack_h2(f.x, f.y), pack_h2(f.z, f.w));
}

// ===========================================================================
// fp16 mma.sync GEMM: C[M,N] = A[M,K] * B[N,K]^T
// CTA tile 128x128, BK=64, 3-stage cp.async pipeline, 1 barrier/iter.
// 256 threads (8 warps: 2m x 4n, 64x32 each). Row stride 144B (128+16 pad).
// ===========================================================================
#define G_STRIDE 144
#define G_ABUF   (128 * G_STRIDE)      // 18432
#define G_STAGE  (2 * G_ABUF)          // 36864
#define GEMM_SMEM (3 * G_STAGE)        // 110592

template<bool F16OUT>
__global__ void __launch_bounds__(256, 2)
gemm_mma(const __half* __restrict__ Ah, const __half* __restrict__ Bh,
         float* __restrict__ C, __half* __restrict__ Ch, int N, int K)
{
    extern __shared__ char smem[];
    const uint32_t sbase = smem_u32(smem);

    const int tid  = threadIdx.x;
    const int lane = tid & 31;
    const int wid  = tid >> 5;
    const int wm   = (wid >> 2) * 64;
    const int wn   = (wid & 3) * 32;
    const int m0   = blockIdx.y * 128;
    const int n0   = blockIdx.x * 128;

    // load map: row = tid>>1, 4 consecutive 16B chunks at (tid&1)*64B
    const int lrow = tid >> 1;
    const int lc   = (tid & 1) * 4;      // chunk index 0 or 4

    const __half* gA = Ah + (size_t)(m0 + lrow) * K + lc * 8;
    const __half* gB = Bh + (size_t)(n0 + lrow) * K + lc * 8;
    const uint32_t drow = lrow * G_STRIDE + lc * 16;

    const int NIT = K >> 6;

    auto issue = [&](int kt) {
        const uint32_t d = sbase + (kt % 3) * G_STAGE + drow;
        const int kb = kt << 6;
#pragma unroll
        for (int c = 0; c < 4; c++) {
            CP16(d + c * 16,          gA + kb + c * 8);
            CP16(d + G_ABUF + c * 16, gB + kb + c * 8);
        }
    };

    issue(0); CP_COMMIT();
    issue(1); CP_COMMIT();

    float acc[4][4][4] = {};

    for (int kt = 0; kt < NIT; kt++) {
        CP_WAIT(1);
        __syncthreads();
        if (kt + 2 < NIT) issue(kt + 2);
        CP_COMMIT();

        const uint32_t sb = sbase + (kt % 3) * G_STAGE;
#pragma unroll
        for (int ks = 0; ks < 4; ks++) {
            uint32_t a4[4][4], b2[4][2];
#pragma unroll
            for (int mi = 0; mi < 4; mi++) {
                uint32_t aaddr = sb + (wm + mi * 16 + (lane & 15)) * G_STRIDE
                               + ks * 32 + (lane >> 4) * 16;
                LDSM4(a4[mi], aaddr);
            }
#pragma unroll
            for (int np = 0; np < 2; np++) {
                uint32_t r[4];
                uint32_t baddr = sb + G_ABUF
                               + (wn + np * 16 + ((lane >> 4) << 3) + (lane & 7)) * G_STRIDE
                               + ks * 32 + ((lane >> 3) & 1) * 16;
                LDSM4(r, baddr);
                b2[np * 2][0]     = r[0]; b2[np * 2][1]     = r[1];
                b2[np * 2 + 1][0] = r[2]; b2[np * 2 + 1][1] = r[3];
            }
#pragma unroll
            for (int mi = 0; mi < 4; mi++)
#pragma unroll
                for (int ni = 0; ni < 4; ni++)
                    MMAF16(acc[mi][ni], a4[mi], b2[ni]);
        }
    }

    const int rg = lane >> 2;
    const int cg = (lane & 3) * 2;
#pragma unroll
    for (int mi = 0; mi < 4; mi++) {
#pragma unroll
        for (int ni = 0; ni < 4; ni++) {
            int r = m0 + wm + mi * 16 + rg;
            int c = n0 + wn + ni * 8 + cg;
            if (F16OUT) {
                *(uint32_t*)&Ch[(size_t)r * N + c] =
                    pack_h2(acc[mi][ni][0], acc[mi][ni][1]);
                *(uint32_t*)&Ch[(size_t)(r + 8) * N + c] =
                    pack_h2(acc[mi][ni][2], acc[mi][ni][3]);
            } else {
                *(float2*)&C[(size_t)r * N + c] =
                    make_float2(acc[mi][ni][0], acc[mi][ni][1]);
                *(float2*)&C[(size_t)(r + 8) * N + c] =
                    make_float2(acc[mi][ni][2], acc[mi][ni][3]);
            }
        }
    }
}

// ===========================================================================
// mma.sync flash attention, causal MQA, fp16. BM=128, BN=128.
// Q persistent; K/V double-buffered. Row stride 272B (256 data + 16 pad).
// ===========================================================================
#define AT_STRIDE 272
#define AT_BUF    (128 * AT_STRIDE)        // 34816 (Q, K, or V tile)
#define AT_STAGE  (2 * AT_BUF)             // K + V
#define AT_KV0    AT_BUF
#define ATTN_SMEM (AT_BUF + 2 * AT_STAGE)  // 174080
#define CSC 0.12751727652f                 // (1/sqrt(128)) * log2(e)

__device__ __forceinline__ void attn_kv_load(uint32_t sb, int st, int tile,
                                             int b, int tid)
{
    const int base = b * SEQ + tile * 128;
    const uint32_t kb = sb + AT_KV0 + st * AT_STAGE;
#pragma unroll
    for (int i = 0; i < 8; i++) {
        int c = tid + i * 256;               // 0..2047
        int row = c >> 4;
        int c16 = c & 15;
        uint32_t dst = kb + row * AT_STRIDE + c16 * 16;
        size_t src = (size_t)(base + row) * QKVN + c16 * 8;
        CP16(dst,          g_qkv + src + 2048);   // K cols [2048,2176)
        CP16(dst + AT_BUF, g_qkv + src + 2176);   // V cols [2176,2304)
    }
}

__global__ void __launch_bounds__(256, 1)
attn_mma()
{
    extern __shared__ char smem[];
    const uint32_t sb = smem_u32(smem);

    const int tid  = threadIdx.x;
    const int lane = tid & 31;
    const int w    = tid >> 5;
    const int qb   = (int)gridDim.x - 1 - (int)blockIdx.x;  // heavy first
    const int b    = blockIdx.y >> 4;
    const int h    = blockIdx.y & 15;
    const int rg   = lane >> 2;
    const int qc   = lane & 3;

    // stage Q (persistent): 128 rows x 128 halves
#pragma unroll
    for (int i = 0; i < 8; i++) {
        int c = tid + i * 256;
        int row = c >> 4;
        int c16 = c & 15;
        size_t src = (size_t)(b * SEQ + qb * 128 + row) * QKVN + h * HD + c16 * 8;
        CP16(sb + row * AT_STRIDE + c16 * 16, g_qkv + src);
    }
    CP_COMMIT();

    const int jmax = qb;
    attn_kv_load(sb, 0, 0, b, tid);
    CP_COMMIT();

    float o[16][4] = {};
    float m0 = -1e30f, m1 = -1e30f, l0 = 0.0f, l1 = 0.0f;

    for (int j = 0; j <= jmax; j++) {
        if (j < jmax) {
            attn_kv_load(sb, (j + 1) & 1, j + 1, b, tid);
            CP_COMMIT();
            CP_WAIT(1);
        } else {
            CP_WAIT(0);
        }
        __syncthreads();

        const uint32_t kvb = sb + AT_KV0 + (j & 1) * AT_STAGE;

        // ---- S = Q K^T : 16 n8 tiles ----
        float s[16][4] = {};
#pragma unroll
        for (int ks = 0; ks < 8; ks++) {
            uint32_t q4[4];
            uint32_t qaddr = sb + (w * 16 + (lane & 15)) * AT_STRIDE
                           + ks * 32 + (lane >> 4) * 16;
            LDSM4(q4, qaddr);
#pragma unroll
            for (int np = 0; np < 8; np++) {
                uint32_t r[4];
                uint32_t kaddr = kvb
                               + (np * 16 + ((lane >> 4) << 3) + (lane & 7)) * AT_STRIDE
                               + ks * 32 + ((lane >> 3) & 1) * 16;
                LDSM4(r, kaddr);
                uint32_t b0[2] = { r[0], r[1] };
                uint32_t b1[2] = { r[2], r[3] };
                MMAF16(s[np * 2],     q4, b0);
                MMAF16(s[np * 2 + 1], q4, b1);
            }
        }

        // ---- causal mask (diagonal tile only) ----
        if (j == qb) {
            const int rbase = qb * 128 + w * 16 + rg;
            const int cbase = j * 128 + qc * 2;
#pragma unroll
            for (int nt = 0; nt < 16; nt++) {
                int c0 = cbase + nt * 8;
                if (c0 > rbase)          s[nt][0] = -1e30f;
                if (c0 + 1 > rbase)      s[nt][1] = -1e30f;
                if (c0 > rbase + 8)      s[nt][2] = -1e30f;
                if (c0 + 1 > rbase + 8)  s[nt][3] = -1e30f;
            }
        }

        // ---- online softmax ----
        float mt0 = -1e30f, mt1 = -1e30f;
#pragma unroll
        for (int nt = 0; nt < 16; nt++) {
            mt0 = fmaxf(mt0, fmaxf(s[nt][0], s[nt][1]));
            mt1 = fmaxf(mt1, fmaxf(s[nt][2], s[nt][3]));
        }
        mt0 = fmaxf(mt0, __shfl_xor_sync(0xffffffff, mt0, 1));
        mt0 = fmaxf(mt0, __shfl_xor_sync(0xffffffff, mt0, 2));
        mt1 = fmaxf(mt1, __shfl_xor_sync(0xffffffff, mt1, 1));
        mt1 = fmaxf(mt1, __shfl_xor_sync(0xffffffff, mt1, 2));

        float m0n = fmaxf(m0, mt0), m1n = fmaxf(m1, mt1);
        float a0 = exp2f((m0 - m0n) * CSC);
        float a1 = exp2f((m1 - m1n) * CSC);

        float ls0 = 0.0f, ls1 = 0.0f;
#pragma unroll
        for (int nt = 0; nt < 16; nt++) {
            s[nt][0] = exp2f((s[nt][0] - m0n) * CSC);
            s[nt][1] = exp2f((s[nt][1] - m0n) * CSC);
            s[nt][2] = exp2f((s[nt][2] - m1n) * CSC);
            s[nt][3] = exp2f((s[nt][3] - m1n) * CSC);
            ls0 += s[nt][0] + s[nt][1];
            ls1 += s[nt][2] + s[nt][3];
        }
        ls0 += __shfl_xor_sync(0xffffffff, ls0, 1);
        ls0 += __shfl_xor_sync(0xffffffff, ls0, 2);
        ls1 += __shfl_xor_sync(0xffffffff, ls1, 1);
        ls1 += __shfl_xor_sync(0xffffffff, ls1, 2);

        l0 = l0 * a0 + ls0;
        l1 = l1 * a1 + ls1;
        m0 = m0n; m1 = m1n;

#pragma unroll
        for (int nt = 0; nt < 16; nt++) {
            o[nt][0] *= a0; o[nt][1] *= a0;
            o[nt][2] *= a1; o[nt][3] *= a1;
        }

        // ---- O += P V ----
#pragma unroll
        for (int kk = 0; kk < 8; kk++) {
            uint32_t p4[4];
            p4[0] = pack_h2(s[2*kk][0],   s[2*kk][1]);
            p4[1] = pack_h2(s[2*kk][2],   s[2*kk][3]);
            p4[2] = pack_h2(s[2*kk+1][0], s[2*kk+1][1]);
            p4[3] = pack_h2(s[2*kk+1][2], s[2*kk+1][3]);
#pragma unroll
            for (int np = 0; np < 8; np++) {
                uint32_t r[4];
                uint32_t vaddr = kvb + AT_BUF
                               + (kk * 16 + (lane & 15)) * AT_STRIDE
                               + (np * 2 + (lane >> 4)) * 16;
                LDSM4T(r, vaddr);
                uint32_t v0[2] = { r[0], r[1] };
                uint32_t v1[2] = { r[2], r[3] };
                MMAF16(o[np * 2],     p4, v0);
                MMAF16(o[np * 2 + 1], p4, v1);
            }
        }
        __syncthreads();
    }

    // ---- normalize, write fp16 ----
    const float inv0 = 1.0f / l0;
    const float inv1 = 1.0f / l1;
    const size_t row0 = (size_t)(b * SEQ + qb * 128 + w * 16 + rg) * DM;
    const size_t row1 = row0 + 8 * DM;
#pragma unroll
    for (int nt = 0; nt < 16; nt++) {
        int col = h * HD + nt * 8 + qc * 2;
        *(uint32_t*)&g_oh[row0 + col] = pack_h2(o[nt][0] * inv0, o[nt][1] * inv0);
        *(uint32_t*)&g_oh[row1 + col] = pack_h2(o[nt][2] * inv1, o[nt][3] * inv1);
    }
}

// ===========================================================================
extern "C" void kernel_launch(void* const* d_in, const int* in_sizes, int n_in,
                              void* d_out, int out_size)
{
    const float* x   = (const float*)d_in[0];
    const float* Wq  = (const float*)d_in[1];
    const float* Wkv = (const float*)d_in[2];
    const float* Wo  = (const float*)d_in[3];
    float* out = (float*)d_out;

    __half *xh, *wqkv, *woh, *qkv, *oh;
    cudaGetSymbolAddress((void**)&xh,   g_xh);
    cudaGetSymbolAddress((void**)&wqkv, g_wqkv);
    cudaGetSymbolAddress((void**)&woh,  g_woh);
    cudaGetSymbolAddress((void**)&qkv,  g_qkv);
    cudaGetSymbolAddress((void**)&oh,   g_oh);

    cudaFuncSetAttribute(gemm_mma<false>,
                         cudaFuncAttributeMaxDynamicSharedMemorySize, GEMM_SMEM);
    cudaFuncSetAttribute(gemm_mma<true>,
                         cudaFuncAttributeMaxDynamicSharedMemorySize, GEMM_SMEM);
    cudaFuncSetAttribute(attn_mma,
                         cudaFuncAttributeMaxDynamicSharedMemorySize, ATTN_SMEM);

    // convert fp32 inputs to fp16 (Wq and Wkv stacked into one buffer)
    {
        int n4 = MTOT * DM / 4;
        cvt_f16<<<(n4 + 255) / 256, 256>>>((const float4*)x, (uint2*)xh, n4);
        n4 = DM * DM / 4;
        cvt_f16<<<(n4 + 255) / 256, 256>>>((const float4*)Wq, (uint2*)wqkv, n4);
        cvt_f16<<<(n4 + 255) / 256, 256>>>((const float4*)Wo, (uint2*)woh, n4);
        n4 = KVD * DM / 4;
        cvt_f16<<<(n4 + 255) / 256, 256>>>((const float4*)Wkv,
                                           (uint2*)(wqkv + (size_t)DM * DM), n4);
    }

    // merged Q+KV projection -> fp16 [MTOT, 2304]
    gemm_mma<true><<<dim3(QKVN / 128, MTOT / 128), 256, GEMM_SMEM>>>(
        xh, wqkv, nullptr, qkv, QKVN, DM);
    // attention -> fp16 [MTOT, 2048]
    attn_mma<<<dim3(SEQ / 128, BATCH * NH), 256, ATTN_SMEM>>>();
    // O projection -> fp32 output
    gemm_mma<false><<<dim3(DM / 128, MTOT / 128), 256, GEMM_SMEM>>>(
        oh, woh, out, nullptr, DM, DM);
}